// round 7
// baseline (speedup 1.0000x reference)
#include <cuda_runtime.h>
#include <cuda_bf16.h>

#define LL 2048
#define BB 64
#define KK 4
#define CC 128
#define II 512
#define NITEMS (II * BB)     // 32768
#define ITEMS_PER_WARP 4
#define NWARPS (NITEMS / ITEMS_PER_WARP)     // 8192
#define NPERM 24
#define WARPS_PER_BLOCK 4
#define NBLOCKS (NWARPS / WARPS_PER_BLOCK)   // 2048

__device__ double g_acc;
__device__ unsigned int g_count;

// permutations of {0,1,2,3}, one byte per position (little-endian)
__constant__ unsigned int c_perms[NPERM] = {
    0x03020100u, 0x02030100u, 0x03010200u, 0x01030200u, 0x02010300u, 0x01020300u,
    0x03020001u, 0x02030001u, 0x03000201u, 0x00030201u, 0x02000301u, 0x00020301u,
    0x03010002u, 0x01030002u, 0x03000102u, 0x00030102u, 0x01000302u, 0x00010302u,
    0x02010003u, 0x01020003u, 0x02000103u, 0x00020103u, 0x01000203u, 0x00010203u
};

__device__ __forceinline__ float exps4(float4 v) {
    return __expf(v.x) + __expf(v.y) + __expf(v.z) + __expf(v.w);
}

__global__ __launch_bounds__(128) void detpp_fused_kernel(
    const float* __restrict__ in_time,     // (L, B)
    const float* __restrict__ in_amount,   // (L, B)
    const int*   __restrict__ in_mcc,      // (L, B)
    const float* __restrict__ out_time,    // (L, B, K)
    const float* __restrict__ out_amount,  // (L, B, K)
    const float* __restrict__ out_logits,  // (L, B, K, C)
    const float* __restrict__ presence,    // (L, B, K)
    const int*   __restrict__ indices,     // (I, B)
    const int*   __restrict__ subset_lengths, // (B,)
    float*       __restrict__ out)
{
    __shared__ double s_acc;
    __shared__ unsigned int s_perms[32];
    __shared__ int s_islast;

    int tid = threadIdx.x;
    if (tid == 0) s_acc = 0.0;
    if (tid < 32) s_perms[tid] = c_perms[tid < NPERM ? tid : 0];
    __syncthreads();

    int gwarp = blockIdx.x * WARPS_PER_BLOCK + (tid >> 5);
    int lane  = tid & 31;
    int hl    = lane & 15;        // lane within half-warp
    int half  = lane >> 4;        // which item of the pair this lane serves
    int k = (lane >> 2) & 3;
    int t = lane & 3;
    int quad = gwarp * ITEMS_PER_WARP;

    // ------------- LOAD PHASE: both pairs issued back-to-back -------------
    float4 v[2][8];                        // [pair][8 float4s]
    float tw0[2], twt[2], awt[2], ot[2], oa[2], ps[2], sel[2];
    int validX[2];

    int c0 = half * CC + hl * 4;
    int c2 = (2 + half) * CC + hl * 4;

    #pragma unroll
    for (int p = 0; p < 2; p++) {
        int it0 = quad + 2 * p, it1 = it0 + 1;
        int b0 = it0 & (BB - 1), i0 = it0 >> 6;
        int b1 = it1 & (BB - 1), i1 = it1 >> 6;
        int valid0 = i0 < subset_lengths[b0];
        int valid1 = i1 < subset_lengths[b1];
        int idx0 = indices[i0 * BB + b0];
        int idx1 = indices[i1 * BB + b1];
        int row0 = idx0 * BB + b0;
        int row1 = idx1 * BB + b1;
        const float* lp0 = out_logits + (size_t)row0 * (KK * CC);
        const float* lp1 = out_logits + (size_t)row1 * (KK * CC);

        v[p][0] = *reinterpret_cast<const float4*>(lp0 + c0);
        v[p][1] = *reinterpret_cast<const float4*>(lp0 + c0 + 64);
        v[p][2] = *reinterpret_cast<const float4*>(lp0 + c2);
        v[p][3] = *reinterpret_cast<const float4*>(lp0 + c2 + 64);
        v[p][4] = *reinterpret_cast<const float4*>(lp1 + c0);
        v[p][5] = *reinterpret_cast<const float4*>(lp1 + c0 + 64);
        v[p][6] = *reinterpret_cast<const float4*>(lp1 + c2);
        v[p][7] = *reinterpret_cast<const float4*>(lp1 + c2 + 64);

        // per-lane item view (half-warp per item)
        int idxX = half ? idx1 : idx0;
        int bX   = half ? b1   : b0;
        int rowX = half ? row1 : row0;
        const float* lpX = half ? lp1 : lp0;
        validX[p] = half ? valid1 : valid0;

        tw0[p] = in_time[rowX];
        int r = idxX + t + 1;
        if (r >= LL) r -= LL;              // roll wrap (unreachable for valid items)
        int rr = r * BB + bX;
        twt[p] = in_time[rr];
        awt[p] = in_amount[rr];
        int cwt = in_mcc[rr];
        int obase = rowX * KK + k;
        ot[p] = out_time[obase];
        oa[p] = out_amount[obase];
        ps[p] = presence[obase];
        sel[p] = lpX[k * CC + cwt];        // dependent load, overlaps other pair
    }

    // ------------- EXP SUMS (consume float4s, free registers) -------------
    float s01[2], s23[2], u01[2], u23[2];
    #pragma unroll
    for (int p = 0; p < 2; p++) {
        s01[p] = exps4(v[p][0]) + exps4(v[p][1]);
        s23[p] = exps4(v[p][2]) + exps4(v[p][3]);
        u01[p] = exps4(v[p][4]) + exps4(v[p][5]);
        u23[p] = exps4(v[p][6]) + exps4(v[p][7]);
    }

    // ------------- 8 interleaved half-warp butterflies -------------
    #pragma unroll
    for (int o = 8; o; o >>= 1) {
        #pragma unroll
        for (int p = 0; p < 2; p++) {
            s01[p] += __shfl_xor_sync(0xffffffffu, s01[p], o);
            s23[p] += __shfl_xor_sync(0xffffffffu, s23[p], o);
            u01[p] += __shfl_xor_sync(0xffffffffu, u01[p], o);
            u23[p] += __shfl_xor_sync(0xffffffffu, u23[p], o);
        }
    }

    float warp_tot = 0.f;

    #pragma unroll
    for (int p = 0; p < 2; p++) {
        // cross-half broadcast of the other half's row sums
        float hs01 = __shfl_xor_sync(0xffffffffu, s01[p], 16);
        float hs23 = __shfl_xor_sync(0xffffffffu, s23[p], 16);
        float hu01 = __shfl_xor_sync(0xffffffffu, u01[p], 16);
        float hu23 = __shfl_xor_sync(0xffffffffu, u23[p], 16);

        // row sums for THIS lane's item
        float r0s = half ? hu01 : s01[p];
        float r1s = half ? u01[p] : hs01;
        float r2s = half ? hu23 : s23[p];
        float r3s = half ? u23[p] : hs23;
        float sk = (k == 0) ? r0s : (k == 1) ? r1s : (k == 2) ? r2s : r3s;

        // cost entry (16 per item, one per lane)
        float cost = __logf(sk) - sel[p]
                   + fabsf(ot[p] - (twt[p] - tw0[p]))
                   + fabsf(oa[p] - awt[p])
                   - ps[p];
        float soft = 0.f;
        if (t == 0) {
            float pp = ps[p];
            soft = (pp > 0.f) ? pp + __logf(1.f + __expf(-pp))
                              : __logf(1.f + __expf(pp));
        }

        // exact assignment: 24 perms per item, 2 perms per lane
        int base = lane & 16;
        unsigned int pm1 = s_perms[hl];
        unsigned int pm2 = s_perms[(hl < 8) ? (hl + 16) : hl];
        float pc1 = 0.f, pc2 = 0.f;
        #pragma unroll
        for (int kk = 0; kk < KK; kk++) {
            int sA = base + (kk << 2) + ((pm1 >> (8 * kk)) & 3);
            int sB = base + (kk << 2) + ((pm2 >> (8 * kk)) & 3);
            pc1 += __shfl_sync(0xffffffffu, cost, sA);
            pc2 += __shfl_sync(0xffffffffu, cost, sB);
        }
        float pc = fminf(pc1, (hl < 8) ? pc2 : 3.4e38f);
        #pragma unroll
        for (int o = 8; o; o >>= 1)
            pc = fminf(pc, __shfl_xor_sync(0xffffffffu, pc, o));

        // softplus sum within half (t==0 lanes are {0,4,8,12}+base)
        soft += __shfl_xor_sync(0xffffffffu, soft, 4);
        soft += __shfl_xor_sync(0xffffffffu, soft, 8);

        float half_tot = validX[p] ? (pc + soft) : 0.f;
        half_tot += __shfl_xor_sync(0xffffffffu, half_tot, 16);
        warp_tot += half_tot;              // lane 0's value is the correct one
    }

    if (lane == 0)
        atomicAdd(&s_acc, (double)warp_tot);

    __syncthreads();

    // ---- grid-level reduction: last block finalizes ----
    if (tid == 0) {
        atomicAdd(&g_acc, s_acc);
        __threadfence();
        unsigned int done = atomicAdd(&g_count, 1u);
        s_islast = (done == (unsigned)(NBLOCKS - 1));
    }
    __syncthreads();

    if (s_islast && tid == 0) {
        double acc = g_acc;
        int vv = 0;
        #pragma unroll
        for (int bb = 0; bb < BB; bb++) vv += subset_lengths[bb];
        out[0] = (float)(acc / (double)vv);
        g_acc = 0.0;                 // reset for next graph replay
        g_count = 0u;
    }
}

extern "C" void kernel_launch(void* const* d_in, const int* in_sizes, int n_in,
                              void* d_out, int out_size)
{
    const float* in_time        = (const float*)d_in[0];
    const float* in_amount      = (const float*)d_in[1];
    const int*   in_mcc         = (const int*)  d_in[2];
    const float* out_time       = (const float*)d_in[3];
    const float* out_amount     = (const float*)d_in[4];
    const float* out_logits     = (const float*)d_in[5];
    const float* presence       = (const float*)d_in[6];
    // d_in[7] = lengths (unused; subset_lengths already encodes validity)
    const int*   indices        = (const int*)  d_in[8];
    const int*   subset_lengths = (const int*)  d_in[9];
    float* out = (float*)d_out;

    detpp_fused_kernel<<<NBLOCKS, 128>>>(
        in_time, in_amount, in_mcc, out_time, out_amount,
        out_logits, presence, indices, subset_lengths, out);
}

// round 8
// speedup vs baseline: 1.1347x; 1.1347x over previous
#include <cuda_runtime.h>
#include <cuda_bf16.h>

#define LL 2048
#define BB 64
#define KK 4
#define CC 128
#define II 512
#define NITEMS (II * BB)     // 32768
#define NPAIRS (NITEMS / 2)  // 16384
#define NPERM 24
#define WARPS_PER_BLOCK 8
#define NBLOCKS 1024                       // single wave: 1024 < 148*8
#define TOTAL_WARPS (NBLOCKS * WARPS_PER_BLOCK)   // 8192
#define PAIRS_PER_WARP (NPAIRS / TOTAL_WARPS)     // 2

__device__ double g_acc;
__device__ unsigned int g_count;

// permutations of {0,1,2,3}, one byte per position (little-endian)
__constant__ unsigned int c_perms[NPERM] = {
    0x03020100u, 0x02030100u, 0x03010200u, 0x01030200u, 0x02010300u, 0x01020300u,
    0x03020001u, 0x02030001u, 0x03000201u, 0x00030201u, 0x02000301u, 0x00020301u,
    0x03010002u, 0x01030002u, 0x03000102u, 0x00030102u, 0x01000302u, 0x00010302u,
    0x02010003u, 0x01020003u, 0x02000103u, 0x00020103u, 0x01000203u, 0x00010203u
};

__device__ __forceinline__ float exps4(float4 v) {
    return __expf(v.x) + __expf(v.y) + __expf(v.z) + __expf(v.w);
}

__global__ __launch_bounds__(256) void detpp_fused_kernel(
    const float* __restrict__ in_time,     // (L, B)
    const float* __restrict__ in_amount,   // (L, B)
    const int*   __restrict__ in_mcc,      // (L, B)
    const float* __restrict__ out_time,    // (L, B, K)
    const float* __restrict__ out_amount,  // (L, B, K)
    const float* __restrict__ out_logits,  // (L, B, K, C)
    const float* __restrict__ presence,    // (L, B, K)
    const int*   __restrict__ indices,     // (I, B)
    const int*   __restrict__ subset_lengths, // (B,)
    float*       __restrict__ out)
{
    __shared__ double s_acc;
    __shared__ unsigned int s_perms[32];
    __shared__ int s_islast;

    int tid = threadIdx.x;
    if (tid == 0) s_acc = 0.0;
    if (tid < 32) s_perms[tid] = c_perms[tid < NPERM ? tid : 0];
    __syncthreads();

    int gwarp = blockIdx.x * WARPS_PER_BLOCK + (tid >> 5);
    int lane  = tid & 31;
    int hl    = lane & 15;        // lane within half-warp
    int half  = lane >> 4;        // 0 = item0, 1 = item1 of the pair
    int k = (lane >> 2) & 3;
    int t = lane & 3;

    int c0 = half * CC + hl * 4;
    int c2 = (2 + half) * CC + hl * 4;

    float warp_tot = 0.f;

    #pragma unroll
    for (int itr = 0; itr < PAIRS_PER_WARP; itr++) {
        int pair = gwarp + itr * TOTAL_WARPS;     // strided: perfectly balanced
        int it0 = pair * 2, it1 = it0 + 1;
        int b0 = it0 & (BB - 1), i0 = it0 >> 6;
        int b1 = it1 & (BB - 1), i1 = it1 >> 6;
        int valid0 = i0 < subset_lengths[b0];
        int valid1 = i1 < subset_lengths[b1];

        int idx0 = indices[i0 * BB + b0];
        int idx1 = indices[i1 * BB + b1];
        int row0 = idx0 * BB + b0;
        int row1 = idx1 * BB + b1;
        const float* lp0 = out_logits + (size_t)row0 * (KK * CC);
        const float* lp1 = out_logits + (size_t)row1 * (KK * CC);

        // ---- logit loads: each instr covers 2 rows, 256B contiguous per half ----
        float4 a01a = *reinterpret_cast<const float4*>(lp0 + c0);
        float4 a01b = *reinterpret_cast<const float4*>(lp0 + c0 + 64);
        float4 a23a = *reinterpret_cast<const float4*>(lp0 + c2);
        float4 a23b = *reinterpret_cast<const float4*>(lp0 + c2 + 64);
        float4 b01a = *reinterpret_cast<const float4*>(lp1 + c0);
        float4 b01b = *reinterpret_cast<const float4*>(lp1 + c0 + 64);
        float4 b23a = *reinterpret_cast<const float4*>(lp1 + c2);
        float4 b23b = *reinterpret_cast<const float4*>(lp1 + c2 + 64);

        // ---- scalar gathers: all 32 lanes active (half-warp per item) ----
        int idxX = half ? idx1 : idx0;
        int bX   = half ? b1   : b0;
        int rowX = half ? row1 : row0;
        const float* lpX = half ? lp1 : lp0;
        int validX = half ? valid1 : valid0;

        float tw0 = in_time[rowX];
        int r = idxX + t + 1;
        if (r >= LL) r -= LL;             // roll wrap (unreachable for valid items)
        int rr = r * BB + bX;
        float twt = in_time[rr];
        float awt = in_amount[rr];
        int   cwt = in_mcc[rr];
        int obase = rowX * KK + k;
        float ot = out_time[obase];
        float oa = out_amount[obase];
        float ps = presence[obase];
        float sel = lpX[k * CC + cwt];

        // ---- exp sums (no max shift: logits ~ N(0,1), fp32-safe) ----
        float s01 = exps4(a01a) + exps4(a01b);    // item0, row (half)
        float s23 = exps4(a23a) + exps4(a23b);    // item0, row (2+half)
        float u01 = exps4(b01a) + exps4(b01b);    // item1
        float u23 = exps4(b23a) + exps4(b23b);

        // ---- 4 interleaved half-warp butterflies (xor 1,2,4,8) ----
        #pragma unroll
        for (int o = 8; o; o >>= 1) {
            s01 += __shfl_xor_sync(0xffffffffu, s01, o);
            s23 += __shfl_xor_sync(0xffffffffu, s23, o);
            u01 += __shfl_xor_sync(0xffffffffu, u01, o);
            u23 += __shfl_xor_sync(0xffffffffu, u23, o);
        }
        // cross-half broadcast: other half's row sums
        float hs01 = __shfl_xor_sync(0xffffffffu, s01, 16);
        float hs23 = __shfl_xor_sync(0xffffffffu, s23, 16);
        float hu01 = __shfl_xor_sync(0xffffffffu, u01, 16);
        float hu23 = __shfl_xor_sync(0xffffffffu, u23, 16);

        // row sums for THIS lane's item
        float r0s = half ? hu01 : s01;
        float r1s = half ? u01  : hs01;
        float r2s = half ? hu23 : s23;
        float r3s = half ? u23  : hs23;
        float sk = (k == 0) ? r0s : (k == 1) ? r1s : (k == 2) ? r2s : r3s;

        // ---- cost entry (16 per item, one per lane) ----
        float cost = __logf(sk) - sel
                   + fabsf(ot - (twt - tw0))
                   + fabsf(oa - awt)
                   - ps;
        float soft = 0.f;
        if (t == 0) {
            soft = (ps > 0.f) ? ps + __logf(1.f + __expf(-ps))
                              : __logf(1.f + __expf(ps));
        }

        // ---- exact assignment: 24 perms per item, 2 perms per lane ----
        int base = lane & 16;
        unsigned int pm1 = s_perms[hl];
        unsigned int pm2 = s_perms[(hl < 8) ? (hl + 16) : hl];
        float pc1 = 0.f, pc2 = 0.f;
        #pragma unroll
        for (int kk = 0; kk < KK; kk++) {
            int sA = base + (kk << 2) + ((pm1 >> (8 * kk)) & 3);
            int sB = base + (kk << 2) + ((pm2 >> (8 * kk)) & 3);
            pc1 += __shfl_sync(0xffffffffu, cost, sA);
            pc2 += __shfl_sync(0xffffffffu, cost, sB);
        }
        float pc = fminf(pc1, (hl < 8) ? pc2 : 3.4e38f);
        #pragma unroll
        for (int o = 8; o; o >>= 1)
            pc = fminf(pc, __shfl_xor_sync(0xffffffffu, pc, o));

        // ---- softplus sum within half (t==0 lanes are {0,4,8,12}+base) ----
        soft += __shfl_xor_sync(0xffffffffu, soft, 4);
        soft += __shfl_xor_sync(0xffffffffu, soft, 8);

        float half_tot = validX ? (pc + soft) : 0.f;
        half_tot += __shfl_xor_sync(0xffffffffu, half_tot, 16);
        warp_tot += half_tot;             // lane 0's value is the correct one
    }

    if (lane == 0)
        atomicAdd(&s_acc, (double)warp_tot);

    __syncthreads();

    // ---- grid-level reduction: last block finalizes ----
    if (tid == 0) {
        atomicAdd(&g_acc, s_acc);
        __threadfence();
        unsigned int done = atomicAdd(&g_count, 1u);
        s_islast = (done == (unsigned)(NBLOCKS - 1));
    }
    __syncthreads();

    if (s_islast && tid == 0) {
        double acc = g_acc;
        int vv = 0;
        #pragma unroll
        for (int bb = 0; bb < BB; bb++) vv += subset_lengths[bb];
        out[0] = (float)(acc / (double)vv);
        g_acc = 0.0;                 // reset for next graph replay
        g_count = 0u;
    }
}

extern "C" void kernel_launch(void* const* d_in, const int* in_sizes, int n_in,
                              void* d_out, int out_size)
{
    const float* in_time        = (const float*)d_in[0];
    const float* in_amount      = (const float*)d_in[1];
    const int*   in_mcc         = (const int*)  d_in[2];
    const float* out_time       = (const float*)d_in[3];
    const float* out_amount     = (const float*)d_in[4];
    const float* out_logits     = (const float*)d_in[5];
    const float* presence       = (const float*)d_in[6];
    // d_in[7] = lengths (unused; subset_lengths already encodes validity)
    const int*   indices        = (const int*)  d_in[8];
    const int*   subset_lengths = (const int*)  d_in[9];
    float* out = (float*)d_out;

    detpp_fused_kernel<<<NBLOCKS, 256>>>(
        in_time, in_amount, in_mcc, out_time, out_amount,
        out_logits, presence, indices, subset_lengths, out);
}